// round 13
// baseline (speedup 1.0000x reference)
#include <cuda_runtime.h>
#include <cuda_bf16.h>
#include <float.h>
#include <stdint.h>

// VectorQuantize: z[16,256,32,32] f32, codebook[8192,256] f32
// bf16 mma.sync GEMM, B-tile resident in smem, 4 row-blocks per CTA (L2 reuse)
// -> per-(row,tile) min + mask -> warp/row select + exact fp32 refine -> gather.

#define NPTS 16384
#define NC   256
#define NK   8192
#define ZQ_ELEMS 4194304
#define TM 128
#define TN 128
#define NTILE (NK / TN)      // 64
#define RB 4                 // row blocks per CTA
#define MARGIN 8e-3f

// ---------------- scratch ----------------
__device__ unsigned short g_ah[NPTS * NC];    // bf16(z)
__device__ unsigned short g_bh[NK * NC];      // bf16(-2cb)
__device__ float g_zf[NPTS * NC];             // fp32 z rows (refine)
__device__ float g_zn[NPTS];
__device__ float g_cn[NK];                    // |cb|^2
__device__ float g_tmin[(size_t)NPTS * NTILE];
__device__ unsigned g_tmask[(size_t)NPTS * NTILE * 4];
__device__ int g_idx[NPTS];

// smem layout for vq_gemm: B resident 4x16KB @0, A dbuf 2x16KB @65536, summaries after
#define SA_OFF  65536
#define SROWMIN 98304   // 128 x u32
#define SMASK   98816   // 128 x 4 x u32
#define SMEM_SZ 100864

// ---------------- PTX helpers ----------------
__device__ __forceinline__ uint32_t smem_u32(const void* p) {
    uint32_t a;
    asm("{ .reg .u64 t; cvta.to.shared.u64 t, %1; cvt.u32.u64 %0, t; }" : "=r"(a) : "l"(p));
    return a;
}
#define CP_ASYNC16(sm, gp) \
    asm volatile("cp.async.cg.shared.global [%0], [%1], 16;" :: "r"(sm), "l"(gp) : "memory")
#define CP_COMMIT() asm volatile("cp.async.commit_group;" ::: "memory")
#define CP_WAIT(n)  asm volatile("cp.async.wait_group %0;" :: "n"(n) : "memory")
#define LDSM_X4(r0, r1, r2, r3, ad) \
    asm volatile("ldmatrix.sync.aligned.m8n8.x4.shared.b16 {%0,%1,%2,%3}, [%4];" \
                 : "=r"(r0), "=r"(r1), "=r"(r2), "=r"(r3) : "r"(ad))
#define MMA16816(d, a0, a1, a2, a3, b0, b1) \
    asm volatile("mma.sync.aligned.m16n8k16.row.col.f32.bf16.bf16.f32 " \
                 "{%0,%1,%2,%3}, {%4,%5,%6,%7}, {%8,%9}, {%0,%1,%2,%3};" \
                 : "+f"((d)[0]), "+f"((d)[1]), "+f"((d)[2]), "+f"((d)[3]) \
                 : "r"(a0), "r"(a1), "r"(a2), "r"(a3), "r"(b0), "r"(b1))

__device__ __forceinline__ uint32_t fenc(float f) {
    uint32_t b = __float_as_uint(f);
    return (b & 0x80000000u) ? ~b : (b | 0x80000000u);
}
__device__ __forceinline__ float fdec(uint32_t u) {
    uint32_t b = (u & 0x80000000u) ? (u & 0x7FFFFFFFu) : ~u;
    return __uint_as_float(b);
}

// ---------------- prep_cb: warp per row, vectorized ----------------
__global__ void __launch_bounds__(256) prep_cb(const float* __restrict__ cb) {
    const int lane = threadIdx.x & 31, wid = threadIdx.x >> 5;
    const int k = blockIdx.x * 8 + wid;
    const float4* row = (const float4*)(cb + (size_t)k * NC);
    float4 v0 = row[lane * 2], v1 = row[lane * 2 + 1];
    float s = v0.x * v0.x + v0.y * v0.y + v0.z * v0.z + v0.w * v0.w
            + v1.x * v1.x + v1.y * v1.y + v1.z * v1.z + v1.w * v1.w;
    uint4 pk;
    {
        uint32_t a, b, c, d;
        asm("cvt.rn.bf16x2.f32 %0, %1, %2;" : "=r"(a) : "f"(-2.0f * v0.y), "f"(-2.0f * v0.x));
        asm("cvt.rn.bf16x2.f32 %0, %1, %2;" : "=r"(b) : "f"(-2.0f * v0.w), "f"(-2.0f * v0.z));
        asm("cvt.rn.bf16x2.f32 %0, %1, %2;" : "=r"(c) : "f"(-2.0f * v1.y), "f"(-2.0f * v1.x));
        asm("cvt.rn.bf16x2.f32 %0, %1, %2;" : "=r"(d) : "f"(-2.0f * v1.w), "f"(-2.0f * v1.z));
        pk.x = a; pk.y = b; pk.z = c; pk.w = d;
    }
    *(uint4*)(g_bh + (size_t)k * NC + lane * 8) = pk;
#pragma unroll
    for (int o = 16; o > 0; o >>= 1) s += __shfl_xor_sync(0xffffffffu, s, o);
    if (lane == 0) g_cn[k] = s;
}

// ---------------- prep_z: transposed, coalesced both sides ----------------
__global__ void __launch_bounds__(256) prep_z(const float* __restrict__ z) {
    __shared__ float S[256][33];
    const int t = threadIdx.x, lane = t & 31, wid = t >> 5;
    const int b = blockIdx.y, hw0 = blockIdx.x * 32;
    const float* zb = z + ((size_t)b << 18);
#pragma unroll
    for (int i = 0; i < 32; i++) {
        const int c = i * 8 + wid;
        S[c][lane] = zb[(c << 10) + hw0 + lane];
    }
    __syncthreads();
#pragma unroll
    for (int r = 0; r < 4; r++) {
        const int nl = r * 8 + wid;
        const int n = (b << 10) + hw0 + nl;
        float sum = 0.f;
#pragma unroll
        for (int j = 0; j < 8; j++) {
            const int c = lane + 32 * j;
            const float v = S[c][nl];
            sum += v * v;
            g_zf[(size_t)n * NC + c] = v;
            __nv_bfloat16 h = __float2bfloat16_rn(v);
            g_ah[(size_t)n * NC + c] = *(unsigned short*)&h;
        }
#pragma unroll
        for (int o = 16; o > 0; o >>= 1) sum += __shfl_xor_sync(0xffffffffu, sum, o);
        if (lane == 0) g_zn[n] = sum;
    }
}

// ---------------- GEMM: B resident, 4 row blocks, 4 warps 64x64 ----------------
__device__ __forceinline__ void issueA(uint32_t sb, int buf,
                                       const unsigned short* A, int kchunk, int t) {
    uint32_t ab = sb + SA_OFF + buf * 16384;
#pragma unroll
    for (int i = 0; i < 8; i++) {
        int e = i * 128 + t;
        int r = e >> 3, ck = e & 7;
        int sw = (ck * 16) ^ ((r & 7) * 16);
        CP_ASYNC16(ab + r * 128 + sw, A + (size_t)r * NC + kchunk * 64 + ck * 8);
    }
}
__device__ __forceinline__ void issueB(uint32_t sb, const unsigned short* B, int kchunk, int t) {
    uint32_t bb = sb + kchunk * 16384;
#pragma unroll
    for (int i = 0; i < 8; i++) {
        int e = i * 128 + t;
        int r = e >> 3, ck = e & 7;
        int sw = (ck * 16) ^ ((r & 7) * 16);
        CP_ASYNC16(bb + r * 128 + sw, B + (size_t)r * NC + kchunk * 64 + ck * 8);
    }
}

__global__ void __launch_bounds__(128) vq_gemm() {
    extern __shared__ char smem[];
    const uint32_t sb = smem_u32(smem);
    const int t = threadIdx.x;
    const int lane = t & 31, wid = t >> 5;
    const int warp_m = wid >> 1, warp_n = wid & 1;   // 2x2 warps -> 64x64 per warp
    const int tile = blockIdx.x;
    const int col0 = tile * TN;
    const int rowblk0 = blockIdx.y * RB;
    const unsigned short* B = g_bh + (size_t)col0 * NC;

    uint32_t* rowmin = (uint32_t*)(smem + SROWMIN);
    uint32_t* maskw  = (uint32_t*)(smem + SMASK);

    // preload full B tile (all K) + A(rb0, kc0); one group
#pragma unroll
    for (int kc = 0; kc < 4; kc++) issueB(sb, B, kc, t);
    issueA(sb, 0, g_ah + (size_t)(rowblk0 * TM) * NC, 0, t);
    CP_COMMIT();

    const float cnv[2] = { __ldg(&g_cn[col0 + warp_n * 64 + 0]), 0.f }; // (unused placeholder)

    for (int rb = 0; rb < RB; rb++) {
        const int row0 = (rowblk0 + rb) * TM;

        float d[4][8][4];
#pragma unroll
        for (int i = 0; i < 4; i++)
#pragma unroll
            for (int j = 0; j < 8; j++)
#pragma unroll
                for (int q = 0; q < 4; q++) d[i][j][q] = 0.f;

        for (int kc = 0; kc < 4; kc++) {
            const int gch = rb * 4 + kc;
            if (gch + 1 < RB * 4) {
                const int ng = gch + 1;
                issueA(sb, ng & 1, g_ah + (size_t)((rowblk0 + (ng >> 2)) * TM) * NC, ng & 3, t);
                CP_COMMIT();
                CP_WAIT(1);
            } else {
                CP_WAIT(0);
            }
            __syncthreads();

            const uint32_t Ab = sb + SA_OFF + (gch & 1) * 16384;
            const uint32_t Bb = sb + kc * 16384;
#pragma unroll
            for (int ks = 0; ks < 4; ks++) {
                const int c2 = ks * 32 + (lane >> 4) * 16;
                uint32_t a[4][4];
#pragma unroll
                for (int mt = 0; mt < 4; mt++) {
                    int row = warp_m * 64 + mt * 16 + (lane & 15);
                    uint32_t ad = Ab + row * 128 + (c2 ^ ((row & 7) * 16));
                    LDSM_X4(a[mt][0], a[mt][1], a[mt][2], a[mt][3], ad);
                }
                uint32_t bq[4][4];
#pragma unroll
                for (int np = 0; np < 4; np++) {
                    int brow = warp_n * 64 + np * 16 + (lane & 15);
                    uint32_t bd = Bb + brow * 128 + (c2 ^ ((brow & 7) * 16));
                    LDSM_X4(bq[np][0], bq[np][1], bq[np][2], bq[np][3], bd);
                }
#pragma unroll
                for (int mt = 0; mt < 4; mt++)
#pragma unroll
                    for (int np = 0; np < 4; np++) {
                        MMA16816(d[mt][np * 2],     a[mt][0], a[mt][1], a[mt][2], a[mt][3],
                                 bq[np][0], bq[np][2]);
                        MMA16816(d[mt][np * 2 + 1], a[mt][0], a[mt][1], a[mt][2], a[mt][3],
                                 bq[np][1], bq[np][3]);
                    }
            }
            __syncthreads();
        }

        // ---- summary epilogue for row block rb ----
        rowmin[t] = fenc(FLT_MAX);
#pragma unroll
        for (int i = 0; i < 4; i++) maskw[i * 128 + t] = 0;
        __syncthreads();

        const int g = lane >> 2, tig = lane & 3;
#pragma unroll
        for (int nt = 0; nt < 8; nt++) {
            const int scol = col0 + warp_n * 64 + nt * 8 + 2 * tig;
            const float cn0 = __ldg(&g_cn[scol]);
            const float cn1 = __ldg(&g_cn[scol + 1]);
#pragma unroll
            for (int mt = 0; mt < 4; mt++) {
                d[mt][nt][0] += cn0; d[mt][nt][1] += cn1;
                d[mt][nt][2] += cn0; d[mt][nt][3] += cn1;
            }
        }
#pragma unroll
        for (int mt = 0; mt < 4; mt++) {
            const int r0 = warp_m * 64 + mt * 16 + g;
            float mn0 = FLT_MAX, mn1 = FLT_MAX;
#pragma unroll
            for (int nt = 0; nt < 8; nt++) {
                mn0 = fminf(mn0, fminf(d[mt][nt][0], d[mt][nt][1]));
                mn1 = fminf(mn1, fminf(d[mt][nt][2], d[mt][nt][3]));
            }
            atomicMin(&rowmin[r0],     fenc(mn0));
            atomicMin(&rowmin[r0 + 8], fenc(mn1));
        }
        __syncthreads();
#pragma unroll
        for (int mt = 0; mt < 4; mt++) {
            const int r0 = warp_m * 64 + mt * 16 + g;
            const float th0 = fdec(rowmin[r0]) + MARGIN;
            const float th1 = fdec(rowmin[r0 + 8]) + MARGIN;
#pragma unroll
            for (int nt = 0; nt < 8; nt++) {
                const int c = warp_n * 64 + nt * 8 + 2 * tig;
                if (d[mt][nt][0] <= th0) atomicOr(&maskw[r0 * 4 + (c >> 5)], 1u << (c & 31));
                if (d[mt][nt][1] <= th0) atomicOr(&maskw[r0 * 4 + ((c + 1) >> 5)], 1u << ((c + 1) & 31));
                if (d[mt][nt][2] <= th1) atomicOr(&maskw[(r0 + 8) * 4 + (c >> 5)], 1u << (c & 31));
                if (d[mt][nt][3] <= th1) atomicOr(&maskw[(r0 + 8) * 4 + ((c + 1) >> 5)], 1u << ((c + 1) & 31));
            }
        }
        __syncthreads();
        g_tmin[(size_t)(row0 + t) * NTILE + tile] = fdec(rowmin[t]);
#pragma unroll
        for (int i = 0; i < 4; i++) {
            int e = i * 128 + t;
            int r = e >> 2, w = e & 3;
            g_tmask[((size_t)(row0 + r) * NTILE + tile) * 4 + w] = maskw[r * 4 + w];
        }
        __syncthreads();
    }
    (void)cnv;
}

// ---------------- select + exact fp32 refine: one warp per row ----------------
__global__ void __launch_bounds__(256) vq_select(const float* __restrict__ cb) {
    const int lane = threadIdx.x & 31;
    const int row = blockIdx.x * 8 + (threadIdx.x >> 5);

    const float* tm = g_tmin + (size_t)row * NTILE;
    const float v0 = tm[lane], v1 = tm[lane + 32];
    float m = fminf(v0, v1);
#pragma unroll
    for (int o = 16; o > 0; o >>= 1) m = fminf(m, __shfl_xor_sync(0xffffffffu, m, o));
    const float thr = m + MARGIN;

    float z8[8];
#pragma unroll
    for (int i = 0; i < 8; i++) z8[i] = g_zf[(size_t)row * NC + lane * 8 + i];
    const float zn = g_zn[row];

    float bv = FLT_MAX;
    int bi = 0x7fffffff;

    unsigned bal[2];
    bal[0] = __ballot_sync(0xffffffffu, v0 <= thr);
    bal[1] = __ballot_sync(0xffffffffu, v1 <= thr);
#pragma unroll
    for (int p = 0; p < 2; p++) {
        unsigned bits = bal[p];
        while (bits) {
            const int tile = p * 32 + (__ffs(bits) - 1);
            bits &= bits - 1;
            const uint4 mk = *(const uint4*)(g_tmask + ((size_t)row * NTILE + tile) * 4);
            unsigned w[4] = { mk.x, mk.y, mk.z, mk.w };
#pragma unroll
            for (int wi = 0; wi < 4; wi++) {
                unsigned ww = w[wi];
                while (ww) {
                    const int b = __ffs(ww) - 1;
                    ww &= ww - 1;
                    const int k = tile * TN + wi * 32 + b;
                    const float* cbr = cb + (size_t)k * NC + lane * 8;
                    float s = 0.f;
#pragma unroll
                    for (int i = 0; i < 8; i++) s = fmaf(z8[i], -2.0f * cbr[i], s);
#pragma unroll
                    for (int o = 16; o > 0; o >>= 1) s += __shfl_xor_sync(0xffffffffu, s, o);
                    const float dd = (s + zn) + g_cn[k];
                    if (dd < bv || (dd == bv && k < bi)) { bv = dd; bi = k; }
                }
            }
        }
    }
    if (lane == 0) g_idx[row] = bi;
}

// ---------------- transposed gather ----------------
__global__ void __launch_bounds__(256) vq_gather(const float* __restrict__ cb,
                                                 float* __restrict__ out) {
    __shared__ float S[256][33];
    __shared__ int sidx[32];
    const int t = threadIdx.x, lane = t & 31, wid = t >> 5;
    const int b = blockIdx.y, hw0 = blockIdx.x * 32;
    if (t < 32) sidx[t] = g_idx[(b << 10) + hw0 + t];
    __syncthreads();
#pragma unroll
    for (int r = 0; r < 4; r++) {
        const int nl = r * 8 + wid;
        const float* cbr = cb + (size_t)sidx[nl] * NC;
#pragma unroll
        for (int j = 0; j < 8; j++) {
            const int c = lane + 32 * j;
            S[c][nl] = cbr[c];
        }
    }
    __syncthreads();
    float* ob = out + ((size_t)b << 18);
#pragma unroll
    for (int i = 0; i < 32; i++) {
        const int c = i * 8 + wid;
        ob[(c << 10) + hw0 + lane] = S[c][lane];
    }
}

__global__ void vq_idx_out(float* __restrict__ out) {
    int n = blockIdx.x * blockDim.x + threadIdx.x;
    out[ZQ_ELEMS + n] = (float)g_idx[n];
}

extern "C" void kernel_launch(void* const* d_in, const int* in_sizes, int n_in,
                              void* d_out, int out_size) {
    const float* z  = (const float*)d_in[0];
    const float* cb = (const float*)d_in[1];
    if (n_in >= 2 && in_sizes[0] == NK * NC && in_sizes[1] == NPTS * NC) {
        const float* tmp = z; z = cb; cb = tmp;
    }
    float* out = (float*)d_out;

    cudaFuncSetAttribute(vq_gemm, cudaFuncAttributeMaxDynamicSharedMemorySize, SMEM_SZ);

    prep_cb<<<NK / 8, 256>>>(cb);
    prep_z<<<dim3(32, 16), 256>>>(z);
    vq_gemm<<<dim3(NTILE, NPTS / TM / RB), 128, SMEM_SZ>>>();
    vq_select<<<NPTS / 8, 256>>>(cb);
    vq_gather<<<dim3(32, 16), 256>>>(cb, out);
    if (out_size >= ZQ_ELEMS + NPTS)
        vq_idx_out<<<NPTS / 256, 256>>>(out);
}